// round 2
// baseline (speedup 1.0000x reference)
#include <cuda_runtime.h>
#include <cstdint>

#define N_TOK 2048
#define C_DIM 1024
#define H_DIM 2048
#define E_NUM 8
#define EPSF 1.1920929e-07f

// ---------------- scratch (static device globals; no allocs) ----------------
__device__ float g_xt[N_TOK * C_DIM];          // rmsnorm(x)
__device__ float g_xs[N_TOK * C_DIM];          // rmsnorm(rmsnorm(x))
__device__ float g_sg[N_TOK];                  // sigmoid shared gate
__device__ float g_scores[N_TOK * E_NUM];      // softmax scores (for aux)
__device__ float g_h[2 * N_TOK * H_DIM];       // per-assignment up output (33.5MB)
__device__ float g_kk[N_TOK * H_DIM];          // shared-expert hidden (16.8MB)
__device__ float g_contrib[2 * N_TOK * C_DIM]; // per-assignment down output (16.8MB)
__device__ int   g_cnt[E_NUM];
__device__ int   g_etok[E_NUM * N_TOK];
__device__ float g_ew[E_NUM * N_TOK];
__device__ int   g_eslot[E_NUM * N_TOK];

// ---------------- zero counters ----------------
__global__ void k_zero() {
    if (threadIdx.x < E_NUM) g_cnt[threadIdx.x] = 0;
}

// ---------------- rmsnorm + gating (1 block per token, 256 thr) ----------------
__global__ void k_gate(const float* __restrict__ x,
                       const float* __restrict__ gate_w,
                       const float* __restrict__ sgw) {
    const int n   = blockIdx.x;
    const int tid = threadIdx.x;
    __shared__ float red[256];
    __shared__ float sc[2];
    __shared__ float logits[9];

    float4 v = reinterpret_cast<const float4*>(x + (size_t)n * C_DIM)[tid];
    float ss = v.x * v.x + v.y * v.y + v.z * v.z + v.w * v.w;
    red[tid] = ss;
    __syncthreads();
    for (int s = 128; s > 0; s >>= 1) {
        if (tid < s) red[tid] += red[tid + s];
        __syncthreads();
    }
    if (tid == 0) {
        float m1 = red[0] * (1.0f / C_DIM);
        float r1 = rsqrtf(m1 + EPSF);
        float m2 = m1 * r1 * r1;          // mean(xt^2)
        sc[0] = r1;
        sc[1] = rsqrtf(m2 + EPSF);
    }
    __syncthreads();
    const float r1 = sc[0], r2 = sc[1];

    float4 xt;
    xt.x = v.x * r1; xt.y = v.y * r1; xt.z = v.z * r1; xt.w = v.w * r1;
    reinterpret_cast<float4*>(g_xt + (size_t)n * C_DIM)[tid] = xt;
    float4 xs;
    xs.x = xt.x * r2; xs.y = xt.y * r2; xs.z = xt.z * r2; xs.w = xt.w * r2;
    reinterpret_cast<float4*>(g_xs + (size_t)n * C_DIM)[tid] = xs;

    float acc[9];
#pragma unroll
    for (int e = 0; e < 8; e++) {
        float4 g = reinterpret_cast<const float4*>(gate_w + (size_t)e * C_DIM)[tid];
        acc[e] = xt.x * g.x + xt.y * g.y + xt.z * g.z + xt.w * g.w;
    }
    {
        float4 g = reinterpret_cast<const float4*>(sgw)[tid];
        acc[8] = xt.x * g.x + xt.y * g.y + xt.z * g.z + xt.w * g.w;
    }
#pragma unroll 1
    for (int e = 0; e < 9; e++) {
        red[tid] = acc[e];
        __syncthreads();
        for (int s = 128; s > 0; s >>= 1) {
            if (tid < s) red[tid] += red[tid + s];
            __syncthreads();
        }
        if (tid == 0) logits[e] = red[0];
        __syncthreads();
    }

    if (tid == 0) {
        float mx = logits[0];
#pragma unroll
        for (int e = 1; e < 8; e++) mx = fmaxf(mx, logits[e]);
        float sum = 0.0f, sv[8];
#pragma unroll
        for (int e = 0; e < 8; e++) { sv[e] = expf(logits[e] - mx); sum += sv[e]; }
        float inv = 1.0f / sum;
#pragma unroll
        for (int e = 0; e < 8; e++) { sv[e] *= inv; g_scores[n * 8 + e] = sv[e]; }
        int i1 = 0;
#pragma unroll
        for (int e = 1; e < 8; e++) if (sv[e] > sv[i1]) i1 = e;
        int i2 = (i1 == 0) ? 1 : 0;
#pragma unroll
        for (int e = 0; e < 8; e++) if (e != i1 && sv[e] > sv[i2]) i2 = e;
        float wa = sv[i1], wb = sv[i2];
        float wi = 1.0f / (wa + wb + 1e-6f);
        int p1 = atomicAdd(&g_cnt[i1], 1);
        g_etok[i1 * N_TOK + p1]  = n;
        g_ew[i1 * N_TOK + p1]    = wa * wi;
        g_eslot[i1 * N_TOK + p1] = 2 * n;
        int p2 = atomicAdd(&g_cnt[i2], 1);
        g_etok[i2 * N_TOK + p2]  = n;
        g_ew[i2 * N_TOK + p2]    = wb * wi;
        g_eslot[i2 * N_TOK + p2] = 2 * n + 1;
        g_sg[n] = 1.0f / (1.0f + expf(-logits[8]));
    }
}

// ---------------- aux loss ----------------
__global__ void k_aux(float* __restrict__ out, int out_size) {
    const int tid = threadIdx.x;
    __shared__ float red[256];
    __shared__ float ssum[8];
    float loc[8] = {0, 0, 0, 0, 0, 0, 0, 0};
    for (int n = tid; n < N_TOK; n += 256) {
#pragma unroll
        for (int e = 0; e < 8; e++) loc[e] += g_scores[n * 8 + e];
    }
#pragma unroll 1
    for (int e = 0; e < 8; e++) {
        red[tid] = loc[e];
        __syncthreads();
        for (int s = 128; s > 0; s >>= 1) {
            if (tid < s) red[tid] += red[tid + s];
            __syncthreads();
        }
        if (tid == 0) ssum[e] = red[0];
        __syncthreads();
    }
    if (tid == 0) {
        float aux = 0.0f;
#pragma unroll
        for (int e = 0; e < 8; e++)
            aux += ((float)g_cnt[e] * 0.5f / N_TOK) * (ssum[e] / N_TOK);
        aux *= (float)E_NUM * 0.01f;
        if (out_size > N_TOK * C_DIM) out[N_TOK * C_DIM] = aux;
    }
}

// ================= GEMM kernels: 128x128 tile, BK=16, 256 thr, 8x8/thread ====
// C[M,N] = A[M,K] @ B[N,K]^T, both K-contiguous.

// ---- expert up: h[slot] = relu(xt[tok] @ w1[e]^T)^2 * w ----
__global__ void __launch_bounds__(256, 2) k_up(const float* __restrict__ w1) {
    const int e = blockIdx.z;
    const int cnt = g_cnt[e];
    const int m0 = blockIdx.y * 128;
    if (m0 >= cnt) return;
    const int n0 = blockIdx.x * 128;
    __shared__ float As[16][128];
    __shared__ float Bs[16][128];
    const int tid = threadIdx.x;
    const int lr = tid >> 2;
    const int lc = (tid & 3) << 2;
    int ma = m0 + lr;       if (ma >= cnt) ma = cnt - 1;
    int mb = m0 + lr + 64;  if (mb >= cnt) mb = cnt - 1;
    const float* A0 = g_xt + (size_t)g_etok[e * N_TOK + ma] * C_DIM;
    const float* A1 = g_xt + (size_t)g_etok[e * N_TOK + mb] * C_DIM;
    const float* B0 = w1 + (size_t)e * H_DIM * C_DIM + (size_t)(n0 + lr) * C_DIM;
    const float* B1 = B0 + (size_t)64 * C_DIM;
    float acc[8][8];
#pragma unroll
    for (int i = 0; i < 8; i++)
#pragma unroll
        for (int j = 0; j < 8; j++) acc[i][j] = 0.0f;
    const int tr = (tid >> 4) << 2;
    const int tc = (tid & 15) << 2;
    for (int k0 = 0; k0 < C_DIM; k0 += 16) {
        float4 a0 = *(const float4*)(A0 + k0 + lc);
        float4 a1 = *(const float4*)(A1 + k0 + lc);
        float4 b0 = *(const float4*)(B0 + k0 + lc);
        float4 b1 = *(const float4*)(B1 + k0 + lc);
        As[lc + 0][lr] = a0.x; As[lc + 1][lr] = a0.y; As[lc + 2][lr] = a0.z; As[lc + 3][lr] = a0.w;
        As[lc + 0][lr + 64] = a1.x; As[lc + 1][lr + 64] = a1.y; As[lc + 2][lr + 64] = a1.z; As[lc + 3][lr + 64] = a1.w;
        Bs[lc + 0][lr] = b0.x; Bs[lc + 1][lr] = b0.y; Bs[lc + 2][lr] = b0.z; Bs[lc + 3][lr] = b0.w;
        Bs[lc + 0][lr + 64] = b1.x; Bs[lc + 1][lr + 64] = b1.y; Bs[lc + 2][lr + 64] = b1.z; Bs[lc + 3][lr + 64] = b1.w;
        __syncthreads();
#pragma unroll
        for (int k = 0; k < 16; k++) {
            float4 ra0 = *(const float4*)&As[k][tr];
            float4 ra1 = *(const float4*)&As[k][tr + 64];
            float4 rb0 = *(const float4*)&Bs[k][tc];
            float4 rb1 = *(const float4*)&Bs[k][tc + 64];
            float ra[8] = {ra0.x, ra0.y, ra0.z, ra0.w, ra1.x, ra1.y, ra1.z, ra1.w};
            float rb[8] = {rb0.x, rb0.y, rb0.z, rb0.w, rb1.x, rb1.y, rb1.z, rb1.w};
#pragma unroll
            for (int i = 0; i < 8; i++)
#pragma unroll
                for (int j = 0; j < 8; j++) acc[i][j] += ra[i] * rb[j];
        }
        __syncthreads();
    }
#pragma unroll
    for (int i = 0; i < 8; i++) {
        int m = m0 + ((i < 4) ? (tr + i) : (64 + tr + i - 4));
        if (m < cnt) {
            int base = e * N_TOK + m;
            int slot = g_eslot[base];
            float w = g_ew[base];
            float* dst = g_h + (size_t)slot * H_DIM + n0;
#pragma unroll
            for (int j = 0; j < 8; j++) {
                int nn = (j < 4) ? (tc + j) : (64 + tc + j - 4);
                float v = fmaxf(acc[i][j], 0.0f);
                dst[nn] = v * v * w;
            }
        }
    }
}

// ---- expert down: contrib[slot] = h[slot] @ w2[e]^T ----
__global__ void __launch_bounds__(256, 2) k_down(const float* __restrict__ w2) {
    const int e = blockIdx.z;
    const int cnt = g_cnt[e];
    const int m0 = blockIdx.y * 128;
    if (m0 >= cnt) return;
    const int n0 = blockIdx.x * 128;
    __shared__ float As[16][128];
    __shared__ float Bs[16][128];
    const int tid = threadIdx.x;
    const int lr = tid >> 2;
    const int lc = (tid & 3) << 2;
    int ma = m0 + lr;       if (ma >= cnt) ma = cnt - 1;
    int mb = m0 + lr + 64;  if (mb >= cnt) mb = cnt - 1;
    const float* A0 = g_h + (size_t)g_eslot[e * N_TOK + ma] * H_DIM;
    const float* A1 = g_h + (size_t)g_eslot[e * N_TOK + mb] * H_DIM;
    const float* B0 = w2 + (size_t)e * C_DIM * H_DIM + (size_t)(n0 + lr) * H_DIM;
    const float* B1 = B0 + (size_t)64 * H_DIM;
    float acc[8][8];
#pragma unroll
    for (int i = 0; i < 8; i++)
#pragma unroll
        for (int j = 0; j < 8; j++) acc[i][j] = 0.0f;
    const int tr = (tid >> 4) << 2;
    const int tc = (tid & 15) << 2;
    for (int k0 = 0; k0 < H_DIM; k0 += 16) {
        float4 a0 = *(const float4*)(A0 + k0 + lc);
        float4 a1 = *(const float4*)(A1 + k0 + lc);
        float4 b0 = *(const float4*)(B0 + k0 + lc);
        float4 b1 = *(const float4*)(B1 + k0 + lc);
        As[lc + 0][lr] = a0.x; As[lc + 1][lr] = a0.y; As[lc + 2][lr] = a0.z; As[lc + 3][lr] = a0.w;
        As[lc + 0][lr + 64] = a1.x; As[lc + 1][lr + 64] = a1.y; As[lc + 2][lr + 64] = a1.z; As[lc + 3][lr + 64] = a1.w;
        Bs[lc + 0][lr] = b0.x; Bs[lc + 1][lr] = b0.y; Bs[lc + 2][lr] = b0.z; Bs[lc + 3][lr] = b0.w;
        Bs[lc + 0][lr + 64] = b1.x; Bs[lc + 1][lr + 64] = b1.y; Bs[lc + 2][lr + 64] = b1.z; Bs[lc + 3][lr + 64] = b1.w;
        __syncthreads();
#pragma unroll
        for (int k = 0; k < 16; k++) {
            float4 ra0 = *(const float4*)&As[k][tr];
            float4 ra1 = *(const float4*)&As[k][tr + 64];
            float4 rb0 = *(const float4*)&Bs[k][tc];
            float4 rb1 = *(const float4*)&Bs[k][tc + 64];
            float ra[8] = {ra0.x, ra0.y, ra0.z, ra0.w, ra1.x, ra1.y, ra1.z, ra1.w};
            float rb[8] = {rb0.x, rb0.y, rb0.z, rb0.w, rb1.x, rb1.y, rb1.z, rb1.w};
#pragma unroll
            for (int i = 0; i < 8; i++)
#pragma unroll
                for (int j = 0; j < 8; j++) acc[i][j] += ra[i] * rb[j];
        }
        __syncthreads();
    }
#pragma unroll
    for (int i = 0; i < 8; i++) {
        int m = m0 + ((i < 4) ? (tr + i) : (64 + tr + i - 4));
        if (m < cnt) {
            int slot = g_eslot[e * N_TOK + m];
            float* dst = g_contrib + (size_t)slot * C_DIM + n0;
#pragma unroll
            for (int j = 0; j < 8; j++) {
                int nn = (j < 4) ? (tc + j) : (64 + tc + j - 4);
                dst[nn] = acc[i][j];
            }
        }
    }
}

// ---- shared expert up: kk = relu(xs @ k_w^T + k_b)^2 ----
__global__ void __launch_bounds__(256, 2) k_sup(const float* __restrict__ kw,
                                                const float* __restrict__ kb) {
    const int m0 = blockIdx.y * 128;
    const int n0 = blockIdx.x * 128;
    __shared__ float As[16][128];
    __shared__ float Bs[16][128];
    const int tid = threadIdx.x;
    const int lr = tid >> 2;
    const int lc = (tid & 3) << 2;
    const float* A0 = g_xs + (size_t)(m0 + lr) * C_DIM;
    const float* A1 = A0 + (size_t)64 * C_DIM;
    const float* B0 = kw + (size_t)(n0 + lr) * C_DIM;
    const float* B1 = B0 + (size_t)64 * C_DIM;
    float acc[8][8];
#pragma unroll
    for (int i = 0; i < 8; i++)
#pragma unroll
        for (int j = 0; j < 8; j++) acc[i][j] = 0.0f;
    const int tr = (tid >> 4) << 2;
    const int tc = (tid & 15) << 2;
    for (int k0 = 0; k0 < C_DIM; k0 += 16) {
        float4 a0 = *(const float4*)(A0 + k0 + lc);
        float4 a1 = *(const float4*)(A1 + k0 + lc);
        float4 b0 = *(const float4*)(B0 + k0 + lc);
        float4 b1 = *(const float4*)(B1 + k0 + lc);
        As[lc + 0][lr] = a0.x; As[lc + 1][lr] = a0.y; As[lc + 2][lr] = a0.z; As[lc + 3][lr] = a0.w;
        As[lc + 0][lr + 64] = a1.x; As[lc + 1][lr + 64] = a1.y; As[lc + 2][lr + 64] = a1.z; As[lc + 3][lr + 64] = a1.w;
        Bs[lc + 0][lr] = b0.x; Bs[lc + 1][lr] = b0.y; Bs[lc + 2][lr] = b0.z; Bs[lc + 3][lr] = b0.w;
        Bs[lc + 0][lr + 64] = b1.x; Bs[lc + 1][lr + 64] = b1.y; Bs[lc + 2][lr + 64] = b1.z; Bs[lc + 3][lr + 64] = b1.w;
        __syncthreads();
#pragma unroll
        for (int k = 0; k < 16; k++) {
            float4 ra0 = *(const float4*)&As[k][tr];
            float4 ra1 = *(const float4*)&As[k][tr + 64];
            float4 rb0 = *(const float4*)&Bs[k][tc];
            float4 rb1 = *(const float4*)&Bs[k][tc + 64];
            float ra[8] = {ra0.x, ra0.y, ra0.z, ra0.w, ra1.x, ra1.y, ra1.z, ra1.w};
            float rb[8] = {rb0.x, rb0.y, rb0.z, rb0.w, rb1.x, rb1.y, rb1.z, rb1.w};
#pragma unroll
            for (int i = 0; i < 8; i++)
#pragma unroll
                for (int j = 0; j < 8; j++) acc[i][j] += ra[i] * rb[j];
        }
        __syncthreads();
    }
#pragma unroll
    for (int i = 0; i < 8; i++) {
        int m = m0 + ((i < 4) ? (tr + i) : (64 + tr + i - 4));
        float* dst = g_kk + (size_t)m * H_DIM + n0;
#pragma unroll
        for (int j = 0; j < 8; j++) {
            int nn = (j < 4) ? (tc + j) : (64 + tc + j - 4);
            float v = acc[i][j] + kb[n0 + nn];
            v = fmaxf(v, 0.0f);
            dst[nn] = v * v;
        }
    }
}

// ---- shared expert down: out = sg * (kk @ v_w^T + v_b) ----
__global__ void __launch_bounds__(256, 2) k_sdown(const float* __restrict__ vw,
                                                  const float* __restrict__ vb,
                                                  float* __restrict__ out) {
    const int m0 = blockIdx.y * 128;
    const int n0 = blockIdx.x * 128;
    __shared__ float As[16][128];
    __shared__ float Bs[16][128];
    const int tid = threadIdx.x;
    const int lr = tid >> 2;
    const int lc = (tid & 3) << 2;
    const float* A0 = g_kk + (size_t)(m0 + lr) * H_DIM;
    const float* A1 = A0 + (size_t)64 * H_DIM;
    const float* B0 = vw + (size_t)(n0 + lr) * H_DIM;
    const float* B1 = B0 + (size_t)64 * H_DIM;
    float acc[8][8];
#pragma unroll
    for (int i = 0; i < 8; i++)
#pragma unroll
        for (int j = 0; j < 8; j++) acc[i][j] = 0.0f;
    const int tr = (tid >> 4) << 2;
    const int tc = (tid & 15) << 2;
    for (int k0 = 0; k0 < H_DIM; k0 += 16) {
        float4 a0 = *(const float4*)(A0 + k0 + lc);
        float4 a1 = *(const float4*)(A1 + k0 + lc);
        float4 b0 = *(const float4*)(B0 + k0 + lc);
        float4 b1 = *(const float4*)(B1 + k0 + lc);
        As[lc + 0][lr] = a0.x; As[lc + 1][lr] = a0.y; As[lc + 2][lr] = a0.z; As[lc + 3][lr] = a0.w;
        As[lc + 0][lr + 64] = a1.x; As[lc + 1][lr + 64] = a1.y; As[lc + 2][lr + 64] = a1.z; As[lc + 3][lr + 64] = a1.w;
        Bs[lc + 0][lr] = b0.x; Bs[lc + 1][lr] = b0.y; Bs[lc + 2][lr] = b0.z; Bs[lc + 3][lr] = b0.w;
        Bs[lc + 0][lr + 64] = b1.x; Bs[lc + 1][lr + 64] = b1.y; Bs[lc + 2][lr + 64] = b1.z; Bs[lc + 3][lr + 64] = b1.w;
        __syncthreads();
#pragma unroll
        for (int k = 0; k < 16; k++) {
            float4 ra0 = *(const float4*)&As[k][tr];
            float4 ra1 = *(const float4*)&As[k][tr + 64];
            float4 rb0 = *(const float4*)&Bs[k][tc];
            float4 rb1 = *(const float4*)&Bs[k][tc + 64];
            float ra[8] = {ra0.x, ra0.y, ra0.z, ra0.w, ra1.x, ra1.y, ra1.z, ra1.w};
            float rb[8] = {rb0.x, rb0.y, rb0.z, rb0.w, rb1.x, rb1.y, rb1.z, rb1.w};
#pragma unroll
            for (int i = 0; i < 8; i++)
#pragma unroll
                for (int j = 0; j < 8; j++) acc[i][j] += ra[i] * rb[j];
        }
        __syncthreads();
    }
#pragma unroll
    for (int i = 0; i < 8; i++) {
        int m = m0 + ((i < 4) ? (tr + i) : (64 + tr + i - 4));
        float sg = g_sg[m];
        float* dst = out + (size_t)m * C_DIM + n0;
#pragma unroll
        for (int j = 0; j < 8; j++) {
            int nn = (j < 4) ? (tc + j) : (64 + tc + j - 4);
            dst[nn] = sg * (acc[i][j] + vb[n0 + nn]);
        }
    }
}

// ---- final combine: out += contrib[2n] + contrib[2n+1] ----
__global__ void k_combine(float* __restrict__ out) {
    const int n = blockIdx.x;
    const int tid = threadIdx.x;
    float4* o = reinterpret_cast<float4*>(out + (size_t)n * C_DIM);
    const float4* c0 = reinterpret_cast<const float4*>(g_contrib + (size_t)(2 * n) * C_DIM);
    const float4* c1 = reinterpret_cast<const float4*>(g_contrib + (size_t)(2 * n + 1) * C_DIM);
    float4 a = o[tid], b = c0[tid], c = c1[tid];
    a.x += b.x + c.x;
    a.y += b.y + c.y;
    a.z += b.z + c.z;
    a.w += b.w + c.w;
    o[tid] = a;
}

// ---------------- launch ----------------
extern "C" void kernel_launch(void* const* d_in, const int* in_sizes, int n_in,
                              void* d_out, int out_size) {
    const float* x   = (const float*)d_in[0];
    const float* gw  = (const float*)d_in[1];
    const float* w1  = (const float*)d_in[2];
    const float* w2  = (const float*)d_in[3];
    const float* sgw = (const float*)d_in[4];
    const float* kw  = (const float*)d_in[5];
    const float* kb  = (const float*)d_in[6];
    const float* vw  = (const float*)d_in[7];
    const float* vb  = (const float*)d_in[8];
    float* out = (float*)d_out;

    k_zero<<<1, 32>>>();
    k_gate<<<N_TOK, 256>>>(x, gw, sgw);
    k_aux<<<1, 256>>>(out, out_size);
    k_up<<<dim3(16, 16, 8), 256>>>(w1);
    k_sup<<<dim3(16, 16), 256>>>(kw, kb);
    k_sdown<<<dim3(8, 16), 256>>>(vw, vb, out);
    k_down<<<dim3(8, 16, 8), 256>>>(w2);
    k_combine<<<N_TOK, 256>>>(out);
}

// round 5
// speedup vs baseline: 3.3848x; 3.3848x over previous
#include <cuda_runtime.h>
#include <cuda_bf16.h>
#include <cstdint>

#define N_TOK 2048
#define C_DIM 1024
#define H_DIM 2048
#define E_NUM 8
#define EPSF 1.1920929e-07f

// ---------------- scratch (static device globals; no allocs) ----------------
__device__ __nv_bfloat16 g_xth[N_TOK * C_DIM], g_xtl[N_TOK * C_DIM];
__device__ __nv_bfloat16 g_xsh[N_TOK * C_DIM], g_xsl[N_TOK * C_DIM];
__device__ __nv_bfloat16 g_w1h[E_NUM * H_DIM * C_DIM], g_w1l[E_NUM * H_DIM * C_DIM];
__device__ __nv_bfloat16 g_w2h[E_NUM * C_DIM * H_DIM], g_w2l[E_NUM * C_DIM * H_DIM];
__device__ __nv_bfloat16 g_kwh[H_DIM * C_DIM], g_kwl[H_DIM * C_DIM];
__device__ __nv_bfloat16 g_vwh[C_DIM * H_DIM], g_vwl[C_DIM * H_DIM];
__device__ __nv_bfloat16 g_hh[2 * N_TOK * H_DIM], g_hl[2 * N_TOK * H_DIM];
__device__ __nv_bfloat16 g_kkh[N_TOK * H_DIM], g_kkl[N_TOK * H_DIM];
__device__ float g_contrib[2 * N_TOK * C_DIM];
__device__ float g_sg[N_TOK];
__device__ float g_scores[N_TOK * E_NUM];
__device__ int   g_cnt[E_NUM];
__device__ int   g_etok[E_NUM * N_TOK];
__device__ float g_ew[E_NUM * N_TOK];
__device__ int   g_eslot[E_NUM * N_TOK];

// ---------------- helpers ----------------
__device__ __forceinline__ unsigned smem_u32(const void* p) {
    unsigned a;
    asm("{ .reg .u64 t; cvta.to.shared.u64 t, %1; cvt.u32.u64 %0, t; }" : "=r"(a) : "l"(p));
    return a;
}

#define CP16(s, g) asm volatile("cp.async.cg.shared.global [%0], [%1], 16;" :: "r"(s), "l"(g))
#define CP_COMMIT() asm volatile("cp.async.commit_group;" ::: "memory")
#define CP_WAIT1() asm volatile("cp.async.wait_group 1;" ::: "memory")
#define CP_WAIT0() asm volatile("cp.async.wait_group 0;" ::: "memory")

__device__ __forceinline__ void ldsm4(unsigned& r0, unsigned& r1, unsigned& r2, unsigned& r3,
                                      unsigned a) {
    asm volatile("ldmatrix.sync.aligned.m8n8.x4.shared.b16 {%0,%1,%2,%3}, [%4];"
                 : "=r"(r0), "=r"(r1), "=r"(r2), "=r"(r3) : "r"(a));
}

__device__ __forceinline__ void hmma(float* c, const unsigned* a, const unsigned* b) {
    asm volatile(
        "mma.sync.aligned.m16n8k16.row.col.f32.bf16.bf16.f32 "
        "{%0,%1,%2,%3}, {%4,%5,%6,%7}, {%8,%9}, {%0,%1,%2,%3};"
        : "+f"(c[0]), "+f"(c[1]), "+f"(c[2]), "+f"(c[3])
        : "r"(a[0]), "r"(a[1]), "r"(a[2]), "r"(a[3]), "r"(b[0]), "r"(b[1]));
}

__device__ __forceinline__ void store_split4(__nv_bfloat16* dh, __nv_bfloat16* dl,
                                             size_t idx, float4 v) {
    __nv_bfloat16 h0 = __float2bfloat16(v.x), h1 = __float2bfloat16(v.y);
    __nv_bfloat16 h2 = __float2bfloat16(v.z), h3 = __float2bfloat16(v.w);
    __nv_bfloat162* p = (__nv_bfloat162*)(dh + idx);
    p[0] = __halves2bfloat162(h0, h1);
    p[1] = __halves2bfloat162(h2, h3);
    __nv_bfloat162* q = (__nv_bfloat162*)(dl + idx);
    q[0] = __halves2bfloat162(__float2bfloat16(v.x - __bfloat162float(h0)),
                              __float2bfloat16(v.y - __bfloat162float(h1)));
    q[1] = __halves2bfloat162(__float2bfloat16(v.z - __bfloat162float(h2)),
                              __float2bfloat16(v.w - __bfloat162float(h3)));
}

// ---------------- zero counters ----------------
__global__ void k_zero() {
    if (threadIdx.x < E_NUM) g_cnt[threadIdx.x] = 0;
}

// ---------------- rmsnorm + gating + bf16 split of xt/xs ----------------
__global__ void k_gate(const float* __restrict__ x,
                       const float* __restrict__ gate_w,
                       const float* __restrict__ sgw) {
    const int n = blockIdx.x, tid = threadIdx.x, wid = tid >> 5, lid = tid & 31;
    __shared__ float part[10][8];
    __shared__ float sc[2];
    __shared__ float logits[9];

    float4 v = reinterpret_cast<const float4*>(x + (size_t)n * C_DIM)[tid];
    float ss = v.x * v.x + v.y * v.y + v.z * v.z + v.w * v.w;
#pragma unroll
    for (int o = 16; o; o >>= 1) ss += __shfl_xor_sync(0xffffffffu, ss, o);
    if (lid == 0) part[9][wid] = ss;
    __syncthreads();
    if (tid == 0) {
        float s = 0;
#pragma unroll
        for (int w = 0; w < 8; w++) s += part[9][w];
        float m1 = s * (1.0f / C_DIM);
        float r1 = rsqrtf(m1 + EPSF);
        sc[0] = r1;
        sc[1] = rsqrtf(m1 * r1 * r1 + EPSF);
    }
    __syncthreads();
    const float r1 = sc[0], r2 = sc[1];

    float4 xt = {v.x * r1, v.y * r1, v.z * r1, v.w * r1};
    float4 xs = {xt.x * r2, xt.y * r2, xt.z * r2, xt.w * r2};
    size_t base = (size_t)n * C_DIM + tid * 4;
    store_split4(g_xth, g_xtl, base, xt);
    store_split4(g_xsh, g_xsl, base, xs);

    float acc[9];
#pragma unroll
    for (int e = 0; e < 8; e++) {
        float4 g = reinterpret_cast<const float4*>(gate_w + (size_t)e * C_DIM)[tid];
        acc[e] = xt.x * g.x + xt.y * g.y + xt.z * g.z + xt.w * g.w;
    }
    {
        float4 g = reinterpret_cast<const float4*>(sgw)[tid];
        acc[8] = xt.x * g.x + xt.y * g.y + xt.z * g.z + xt.w * g.w;
    }
#pragma unroll
    for (int e = 0; e < 9; e++) {
        float a = acc[e];
#pragma unroll
        for (int o = 16; o; o >>= 1) a += __shfl_xor_sync(0xffffffffu, a, o);
        if (lid == 0) part[e][wid] = a;
    }
    __syncthreads();
    if (wid == 0 && lid < 9) {
        float s = 0;
#pragma unroll
        for (int w = 0; w < 8; w++) s += part[lid][w];
        logits[lid] = s;
    }
    __syncthreads();

    if (tid == 0) {
        float mx = logits[0];
#pragma unroll
        for (int e = 1; e < 8; e++) mx = fmaxf(mx, logits[e]);
        float sum = 0.0f, sv[8];
#pragma unroll
        for (int e = 0; e < 8; e++) { sv[e] = expf(logits[e] - mx); sum += sv[e]; }
        float inv = 1.0f / sum;
#pragma unroll
        for (int e = 0; e < 8; e++) { sv[e] *= inv; g_scores[n * 8 + e] = sv[e]; }
        int i1 = 0;
#pragma unroll
        for (int e = 1; e < 8; e++) if (sv[e] > sv[i1]) i1 = e;
        int i2 = (i1 == 0) ? 1 : 0;
#pragma unroll
        for (int e = 0; e < 8; e++) if (e != i1 && sv[e] > sv[i2]) i2 = e;
        float wa = sv[i1], wb = sv[i2];
        float wi = 1.0f / (wa + wb + 1e-6f);
        int p1 = atomicAdd(&g_cnt[i1], 1);
        g_etok[i1 * N_TOK + p1] = n;
        g_ew[i1 * N_TOK + p1] = wa * wi;
        g_eslot[i1 * N_TOK + p1] = 2 * n;
        int p2 = atomicAdd(&g_cnt[i2], 1);
        g_etok[i2 * N_TOK + p2] = n;
        g_ew[i2 * N_TOK + p2] = wb * wi;
        g_eslot[i2 * N_TOK + p2] = 2 * n + 1;
        g_sg[n] = 1.0f / (1.0f + expf(-logits[8]));
    }
}

// ---------------- aux loss ----------------
__global__ void k_aux(float* __restrict__ out, int out_size) {
    const int tid = threadIdx.x;
    __shared__ float red[256];
    __shared__ float ssum[8];
    float loc[8] = {0, 0, 0, 0, 0, 0, 0, 0};
    for (int n = tid; n < N_TOK; n += 256) {
#pragma unroll
        for (int e = 0; e < 8; e++) loc[e] += g_scores[n * 8 + e];
    }
#pragma unroll 1
    for (int e = 0; e < 8; e++) {
        red[tid] = loc[e];
        __syncthreads();
        for (int s = 128; s > 0; s >>= 1) {
            if (tid < s) red[tid] += red[tid + s];
            __syncthreads();
        }
        if (tid == 0) ssum[e] = red[0];
        __syncthreads();
    }
    if (tid == 0) {
        float aux = 0.0f;
#pragma unroll
        for (int e = 0; e < 8; e++)
            aux += ((float)g_cnt[e] * 0.5f / N_TOK) * (ssum[e] / N_TOK);
        aux *= (float)E_NUM * 0.01f;
        if (out_size > N_TOK * C_DIM) out[N_TOK * C_DIM] = aux;
    }
}

// ---------------- fp32 -> bf16 hi/lo split conversion ----------------
template <int W>
__global__ void k_conv(const float4* __restrict__ src, int n4) {
    __nv_bfloat162* dh;
    __nv_bfloat162* dl;
    if (W == 0) { dh = (__nv_bfloat162*)g_w1h; dl = (__nv_bfloat162*)g_w1l; }
    else if (W == 1) { dh = (__nv_bfloat162*)g_w2h; dl = (__nv_bfloat162*)g_w2l; }
    else if (W == 2) { dh = (__nv_bfloat162*)g_kwh; dl = (__nv_bfloat162*)g_kwl; }
    else { dh = (__nv_bfloat162*)g_vwh; dl = (__nv_bfloat162*)g_vwl; }
    int stride = gridDim.x * blockDim.x;
    for (int i = blockIdx.x * blockDim.x + threadIdx.x; i < n4; i += stride) {
        float4 v = src[i];
        __nv_bfloat16 h0 = __float2bfloat16(v.x), h1 = __float2bfloat16(v.y);
        __nv_bfloat16 h2 = __float2bfloat16(v.z), h3 = __float2bfloat16(v.w);
        dh[2 * i] = __halves2bfloat162(h0, h1);
        dh[2 * i + 1] = __halves2bfloat162(h2, h3);
        dl[2 * i] = __halves2bfloat162(__float2bfloat16(v.x - __bfloat162float(h0)),
                                       __float2bfloat16(v.y - __bfloat162float(h1)));
        dl[2 * i + 1] = __halves2bfloat162(__float2bfloat16(v.z - __bfloat162float(h2)),
                                           __float2bfloat16(v.w - __bfloat162float(h3)));
    }
}

// ================= HMMA split-bf16 GEMM =================
// C[128,128] block tile, BK=32, 256 thr (8 warps, 2x4 -> warp tile 64x32).
// 3-pass split: Ah*Bh + Ah*Bl + Al*Bh, fp32 accum (mma.sync m16n8k16 bf16).
#define BKC 32
#define ROWB 80                  // smem row stride bytes (conflict-free ldmatrix)
#define MAT_SZ (128 * ROWB)      // 10240 B per matrix tile
#define SA_H 0
#define SA_L MAT_SZ
#define SB_H (2 * MAT_SZ)
#define SB_L (3 * MAT_SZ)
#define BUF_SZ (4 * MAT_SZ)      // 40960
#define DSMEM_SZ (2 * BUF_SZ)    // 81920

// MODE 0: expert up   A=xt  B=w1[e] K=1024 -> h (relu^2 * w, split bf16)
// MODE 1: expert down A=h   B=w2[e] K=2048 -> contrib (fp32)
// MODE 2: shared up   A=xs  B=kw    K=1024 -> kk ((x+b) relu^2, split bf16)
// MODE 3: shared down A=kk  B=vw    K=2048 -> out = sg*(x+b)
template <int MODE>
__global__ void __launch_bounds__(256, 1) k_mma(const float* __restrict__ bias,
                                                float* __restrict__ outp) {
    extern __shared__ char dsm[];
    __shared__ int s_row[128];
    __shared__ int s_slot[128];
    __shared__ float s_w[128];

    const int e = blockIdx.z;
    const int cnt = (MODE < 2) ? g_cnt[e] : N_TOK;
    const int m0 = blockIdx.y * 128;
    if (m0 >= cnt) return;
    const int n0 = blockIdx.x * 128;
    const int K = (MODE == 0 || MODE == 2) ? C_DIM : H_DIM;

    const __nv_bfloat16 *Ah, *Al, *Bh, *Bl;
    if (MODE == 0) {
        Ah = g_xth; Al = g_xtl;
        Bh = g_w1h + (size_t)e * H_DIM * C_DIM;
        Bl = g_w1l + (size_t)e * H_DIM * C_DIM;
    } else if (MODE == 1) {
        Ah = g_hh; Al = g_hl;
        Bh = g_w2h + (size_t)e * C_DIM * H_DIM;
        Bl = g_w2l + (size_t)e * C_DIM * H_DIM;
    } else if (MODE == 2) {
        Ah = g_xsh; Al = g_xsl; Bh = g_kwh; Bl = g_kwl;
    } else {
        Ah = g_kkh; Al = g_kkl; Bh = g_vwh; Bl = g_vwl;
    }

    const int tid = threadIdx.x, wid = tid >> 5, lid = tid & 31;
    const int wm = wid >> 2, wn = wid & 3;   // warp grid 2(M) x 4(N)

    if (tid < 128) {
        int mi = m0 + tid;
        if (mi >= cnt) mi = cnt - 1;
        if (MODE == 0) {
            s_row[tid] = g_etok[e * N_TOK + mi];
            s_slot[tid] = g_eslot[e * N_TOK + mi];
            s_w[tid] = g_ew[e * N_TOK + mi];
        } else if (MODE == 1) {
            int sl = g_eslot[e * N_TOK + mi];
            s_row[tid] = sl;
            s_slot[tid] = sl;
        } else {
            s_row[tid] = mi;
        }
    }
    __syncthreads();

    const unsigned sbase = smem_u32(dsm);
    const int lr = tid >> 2;          // 0..63 row group for loads (2 iters cover 128)
    const int lcb = (tid & 3) << 4;   // 0,16,32,48 byte col
    const int lce = (tid & 3) << 3;   // element col (bf16)

    // ---- async load of chunk c into buffer b ----
    auto load_chunk = [&](int c, int b) {
        const int kc = c * BKC;
        const unsigned bufb = sbase + b * BUF_SZ;
#pragma unroll
        for (int i = 0; i < 2; i++) {
            const int r = lr + i * 64;
            const unsigned so = r * ROWB + lcb;
            const size_t ga = (size_t)s_row[r] * K + kc + lce;
            CP16(bufb + SA_H + so, Ah + ga);
            CP16(bufb + SA_L + so, Al + ga);
            const size_t gb = (size_t)(n0 + r) * K + kc + lce;
            CP16(bufb + SB_H + so, Bh + gb);
            CP16(bufb + SB_L + so, Bl + gb);
        }
        CP_COMMIT();
    };

    float acc[4][4][4];
#pragma unroll
    for (int i = 0; i < 4; i++)
#pragma unroll
        for (int j = 0; j < 4; j++)
#pragma unroll
            for (int q = 0; q < 4; q++) acc[i][j][q] = 0.0f;

    // ldmatrix lane address components (relative to matrix base within buffer)
    const unsigned aoff = (unsigned)((wm * 64 + (lid & 7) + ((lid >> 3) & 1) * 8) * ROWB +
                                     ((lid >> 4) & 1) * 16);
    const unsigned boff = (unsigned)((wn * 32 + (lid & 7) + ((lid >> 4) & 1) * 8) * ROWB +
                                     ((lid >> 3) & 1) * 16);
    const int NC = K / BKC;
    load_chunk(0, 0);

    for (int c = 0; c < NC; c++) {
        const int b = c & 1;
        if (c + 1 < NC) { load_chunk(c + 1, b ^ 1); CP_WAIT1(); }
        else CP_WAIT0();
        __syncthreads();
        const unsigned bufb = sbase + b * BUF_SZ;
#pragma unroll
        for (int k16 = 0; k16 < 2; k16++) {
            const unsigned kb = k16 * 32;
            unsigned ah[4][4], al[4][4], bh[4][2], bl[4][2];
#pragma unroll
            for (int mt = 0; mt < 4; mt++) {
                const unsigned a = bufb + aoff + mt * (16 * ROWB) + kb;
                ldsm4(ah[mt][0], ah[mt][1], ah[mt][2], ah[mt][3], a + SA_H);
                ldsm4(al[mt][0], al[mt][1], al[mt][2], al[mt][3], a + SA_L);
            }
#pragma unroll
            for (int pr = 0; pr < 2; pr++) {
                const unsigned a = bufb + boff + pr * (16 * ROWB) + kb;
                ldsm4(bh[2 * pr][0], bh[2 * pr][1], bh[2 * pr + 1][0], bh[2 * pr + 1][1], a + SB_H);
                ldsm4(bl[2 * pr][0], bl[2 * pr][1], bl[2 * pr + 1][0], bl[2 * pr + 1][1], a + SB_L);
            }
#pragma unroll
            for (int mt = 0; mt < 4; mt++)
#pragma unroll
                for (int nt = 0; nt < 4; nt++) {
                    hmma(acc[mt][nt], ah[mt], bh[nt]);
                    hmma(acc[mt][nt], ah[mt], bl[nt]);
                    hmma(acc[mt][nt], al[mt], bh[nt]);
                }
        }
        __syncthreads();
    }

    // ---------------- epilogue ----------------
    const int rbase = wm * 64 + (lid >> 2);
    const int cbase = n0 + wn * 32 + 2 * (lid & 3);
#pragma unroll
    for (int mt = 0; mt < 4; mt++) {
#pragma unroll
        for (int half = 0; half < 2; half++) {
            const int rl = rbase + mt * 16 + half * 8;   // local row 0..127
            if (MODE < 2 && m0 + rl >= cnt) continue;
#pragma unroll
            for (int nt = 0; nt < 4; nt++) {
                const int cg = cbase + nt * 8;
                float v0 = acc[mt][nt][2 * half];
                float v1 = acc[mt][nt][2 * half + 1];
                if (MODE == 0) {
                    const float w = s_w[rl];
                    const int slot = s_slot[rl];
                    v0 = fmaxf(v0, 0.0f); v0 = v0 * v0 * w;
                    v1 = fmaxf(v1, 0.0f); v1 = v1 * v1 * w;
                    __nv_bfloat16 h0 = __float2bfloat16(v0), h1 = __float2bfloat16(v1);
                    *(__nv_bfloat162*)(g_hh + (size_t)slot * H_DIM + cg) = __halves2bfloat162(h0, h1);
                    *(__nv_bfloat162*)(g_hl + (size_t)slot * H_DIM + cg) =
                        __halves2bfloat162(__float2bfloat16(v0 - __bfloat162float(h0)),
                                           __float2bfloat16(v1 - __bfloat162float(h1)));
                } else if (MODE == 1) {
                    const int slot = s_slot[rl];
                    *(float2*)(g_contrib + (size_t)slot * C_DIM + cg) = make_float2(v0, v1);
                } else if (MODE == 2) {
                    const int m = m0 + rl;
                    v0 += bias[cg]; v1 += bias[cg + 1];
                    v0 = fmaxf(v0, 0.0f); v0 = v0 * v0;
                    v1 = fmaxf(v1, 0.0f); v1 = v1 * v1;
                    __nv_bfloat16 h0 = __float2bfloat16(v0), h1 = __float2bfloat16(v1);
                    *(__nv_bfloat162*)(g_kkh + (size_t)m * H_DIM + cg) = __halves2bfloat162(h0, h1);
                    *(__nv_bfloat162*)(g_kkl + (size_t)m * H_DIM + cg) =
                        __halves2bfloat162(__float2bfloat16(v0 - __bfloat162float(h0)),
                                           __float2bfloat16(v1 - __bfloat162float(h1)));
                } else {
                    const int m = m0 + rl;
                    const float sg = g_sg[m];
                    *(float2*)(outp + (size_t)m * C_DIM + cg) =
                        make_float2(sg * (v0 + bias[cg]), sg * (v1 + bias[cg + 1]));
                }
            }
        }
    }
}

// ---- final combine: out += contrib[2n] + contrib[2n+1] ----
__global__ void k_combine(float* __restrict__ out) {
    const int n = blockIdx.x;
    const int tid = threadIdx.x;
    float4* o = reinterpret_cast<float4*>(out + (size_t)n * C_DIM);
    const float4* c0 = reinterpret_cast<const float4*>(g_contrib + (size_t)(2 * n) * C_DIM);
    const float4* c1 = reinterpret_cast<const float4*>(g_contrib + (size_t)(2 * n + 1) * C_DIM);
    float4 a = o[tid], b = c0[tid], c = c1[tid];
    a.x += b.x + c.x;
    a.y += b.y + c.y;
    a.z += b.z + c.z;
    a.w += b.w + c.w;
    o[tid] = a;
}

// ---------------- launch ----------------
extern "C" void kernel_launch(void* const* d_in, const int* in_sizes, int n_in,
                              void* d_out, int out_size) {
    const float* x   = (const float*)d_in[0];
    const float* gw  = (const float*)d_in[1];
    const float* w1  = (const float*)d_in[2];
    const float* w2  = (const float*)d_in[3];
    const float* sgw = (const float*)d_in[4];
    const float* kw  = (const float*)d_in[5];
    const float* kb  = (const float*)d_in[6];
    const float* vw  = (const float*)d_in[7];
    const float* vb  = (const float*)d_in[8];
    float* out = (float*)d_out;

    static int attr_done = 0;
    if (!attr_done) {
        cudaFuncSetAttribute(k_mma<0>, cudaFuncAttributeMaxDynamicSharedMemorySize, DSMEM_SZ);
        cudaFuncSetAttribute(k_mma<1>, cudaFuncAttributeMaxDynamicSharedMemorySize, DSMEM_SZ);
        cudaFuncSetAttribute(k_mma<2>, cudaFuncAttributeMaxDynamicSharedMemorySize, DSMEM_SZ);
        cudaFuncSetAttribute(k_mma<3>, cudaFuncAttributeMaxDynamicSharedMemorySize, DSMEM_SZ);
        attr_done = 1;
    }

    k_zero<<<1, 32>>>();
    k_gate<<<N_TOK, 256>>>(x, gw, sgw);
    k_aux<<<1, 256>>>(out, out_size);

    k_conv<0><<<2048, 256>>>((const float4*)w1, E_NUM * H_DIM * C_DIM / 4);
    k_conv<1><<<2048, 256>>>((const float4*)w2, E_NUM * C_DIM * H_DIM / 4);
    k_conv<2><<<256, 256>>>((const float4*)kw, H_DIM * C_DIM / 4);
    k_conv<3><<<256, 256>>>((const float4*)vw, C_DIM * H_DIM / 4);

    k_mma<0><<<dim3(16, 16, 8), 256, DSMEM_SZ>>>(nullptr, nullptr);  // expert up
    k_mma<2><<<dim3(16, 16, 1), 256, DSMEM_SZ>>>(kb, nullptr);       // shared up
    k_mma<1><<<dim3(8, 16, 8), 256, DSMEM_SZ>>>(nullptr, nullptr);   // expert down
    k_mma<3><<<dim3(8, 16, 1), 256, DSMEM_SZ>>>(vb, out);            // shared down
    k_combine<<<N_TOK, 256>>>(out);
}

// round 6
// speedup vs baseline: 3.7109x; 1.0963x over previous
#include <cuda_runtime.h>
#include <cuda_bf16.h>
#include <cstdint>

#define N_TOK 2048
#define C_DIM 1024
#define H_DIM 2048
#define E_NUM 8
#define EPSF 1.1920929e-07f

// ---------------- scratch (static device globals; no allocs) ----------------
__device__ __nv_bfloat16 g_xth[N_TOK * C_DIM], g_xtl[N_TOK * C_DIM];
__device__ __nv_bfloat16 g_xsh[N_TOK * C_DIM], g_xsl[N_TOK * C_DIM];
__device__ __nv_bfloat16 g_w1h[E_NUM * H_DIM * C_DIM], g_w1l[E_NUM * H_DIM * C_DIM];
__device__ __nv_bfloat16 g_w2h[E_NUM * C_DIM * H_DIM], g_w2l[E_NUM * C_DIM * H_DIM];
__device__ __nv_bfloat16 g_kwh[H_DIM * C_DIM], g_kwl[H_DIM * C_DIM];
__device__ __nv_bfloat16 g_vwh[C_DIM * H_DIM], g_vwl[C_DIM * H_DIM];
__device__ __nv_bfloat16 g_hh[2 * N_TOK * H_DIM], g_hl[2 * N_TOK * H_DIM];
__device__ __nv_bfloat16 g_kkh[N_TOK * H_DIM], g_kkl[N_TOK * H_DIM];
__device__ float g_contrib[2 * N_TOK * C_DIM];
__device__ float g_sg[N_TOK];
__device__ float g_scores[N_TOK * E_NUM];
__device__ int   g_cnt[E_NUM];
__device__ int   g_etok[E_NUM * N_TOK];
__device__ float g_ew[E_NUM * N_TOK];
__device__ int   g_eslot[E_NUM * N_TOK];

// ---------------- helpers ----------------
__device__ __forceinline__ unsigned smem_u32(const void* p) {
    unsigned a;
    asm("{ .reg .u64 t; cvta.to.shared.u64 t, %1; cvt.u32.u64 %0, t; }" : "=r"(a) : "l"(p));
    return a;
}

#define CP16(s, g) asm volatile("cp.async.cg.shared.global [%0], [%1], 16;" :: "r"(s), "l"(g))
#define CP_COMMIT() asm volatile("cp.async.commit_group;" ::: "memory")
#define CP_WAIT1() asm volatile("cp.async.wait_group 1;" ::: "memory")
#define CP_WAIT0() asm volatile("cp.async.wait_group 0;" ::: "memory")

__device__ __forceinline__ void ldsm4(unsigned& r0, unsigned& r1, unsigned& r2, unsigned& r3,
                                      unsigned a) {
    asm volatile("ldmatrix.sync.aligned.m8n8.x4.shared.b16 {%0,%1,%2,%3}, [%4];"
                 : "=r"(r0), "=r"(r1), "=r"(r2), "=r"(r3) : "r"(a));
}

__device__ __forceinline__ void hmma(float* c, const unsigned* a, const unsigned* b) {
    asm volatile(
        "mma.sync.aligned.m16n8k16.row.col.f32.bf16.bf16.f32 "
        "{%0,%1,%2,%3}, {%4,%5,%6,%7}, {%8,%9}, {%0,%1,%2,%3};"
        : "+f"(c[0]), "+f"(c[1]), "+f"(c[2]), "+f"(c[3])
        : "r"(a[0]), "r"(a[1]), "r"(a[2]), "r"(a[3]), "r"(b[0]), "r"(b[1]));
}

__device__ __forceinline__ void store_split4(__nv_bfloat16* dh, __nv_bfloat16* dl,
                                             size_t idx, float4 v) {
    __nv_bfloat16 h0 = __float2bfloat16(v.x), h1 = __float2bfloat16(v.y);
    __nv_bfloat16 h2 = __float2bfloat16(v.z), h3 = __float2bfloat16(v.w);
    __nv_bfloat162* p = (__nv_bfloat162*)(dh + idx);
    p[0] = __halves2bfloat162(h0, h1);
    p[1] = __halves2bfloat162(h2, h3);
    __nv_bfloat162* q = (__nv_bfloat162*)(dl + idx);
    q[0] = __halves2bfloat162(__float2bfloat16(v.x - __bfloat162float(h0)),
                              __float2bfloat16(v.y - __bfloat162float(h1)));
    q[1] = __halves2bfloat162(__float2bfloat16(v.z - __bfloat162float(h2)),
                              __float2bfloat16(v.w - __bfloat162float(h3)));
}

// ---------------- zero counters ----------------
__global__ void k_zero() {
    if (threadIdx.x < E_NUM) g_cnt[threadIdx.x] = 0;
}

// ---------------- rmsnorm + gating + bf16 split of xt/xs ----------------
__global__ void k_gate(const float* __restrict__ x,
                       const float* __restrict__ gate_w,
                       const float* __restrict__ sgw) {
    const int n = blockIdx.x, tid = threadIdx.x, wid = tid >> 5, lid = tid & 31;
    __shared__ float part[10][8];
    __shared__ float sc[2];
    __shared__ float logits[9];

    float4 v = reinterpret_cast<const float4*>(x + (size_t)n * C_DIM)[tid];
    float ss = v.x * v.x + v.y * v.y + v.z * v.z + v.w * v.w;
#pragma unroll
    for (int o = 16; o; o >>= 1) ss += __shfl_xor_sync(0xffffffffu, ss, o);
    if (lid == 0) part[9][wid] = ss;
    __syncthreads();
    if (tid == 0) {
        float s = 0;
#pragma unroll
        for (int w = 0; w < 8; w++) s += part[9][w];
        float m1 = s * (1.0f / C_DIM);
        float r1 = rsqrtf(m1 + EPSF);
        sc[0] = r1;
        sc[1] = rsqrtf(m1 * r1 * r1 + EPSF);
    }
    __syncthreads();
    const float r1 = sc[0], r2 = sc[1];

    float4 xt = {v.x * r1, v.y * r1, v.z * r1, v.w * r1};
    float4 xs = {xt.x * r2, xt.y * r2, xt.z * r2, xt.w * r2};
    size_t base = (size_t)n * C_DIM + tid * 4;
    store_split4(g_xth, g_xtl, base, xt);
    store_split4(g_xsh, g_xsl, base, xs);

    float acc[9];
#pragma unroll
    for (int e = 0; e < 8; e++) {
        float4 g = reinterpret_cast<const float4*>(gate_w + (size_t)e * C_DIM)[tid];
        acc[e] = xt.x * g.x + xt.y * g.y + xt.z * g.z + xt.w * g.w;
    }
    {
        float4 g = reinterpret_cast<const float4*>(sgw)[tid];
        acc[8] = xt.x * g.x + xt.y * g.y + xt.z * g.z + xt.w * g.w;
    }
#pragma unroll
    for (int e = 0; e < 9; e++) {
        float a = acc[e];
#pragma unroll
        for (int o = 16; o; o >>= 1) a += __shfl_xor_sync(0xffffffffu, a, o);
        if (lid == 0) part[e][wid] = a;
    }
    __syncthreads();
    if (wid == 0 && lid < 9) {
        float s = 0;
#pragma unroll
        for (int w = 0; w < 8; w++) s += part[lid][w];
        logits[lid] = s;
    }
    __syncthreads();

    if (tid == 0) {
        float mx = logits[0];
#pragma unroll
        for (int e = 1; e < 8; e++) mx = fmaxf(mx, logits[e]);
        float sum = 0.0f, sv[8];
#pragma unroll
        for (int e = 0; e < 8; e++) { sv[e] = expf(logits[e] - mx); sum += sv[e]; }
        float inv = 1.0f / sum;
#pragma unroll
        for (int e = 0; e < 8; e++) { sv[e] *= inv; g_scores[n * 8 + e] = sv[e]; }
        int i1 = 0;
#pragma unroll
        for (int e = 1; e < 8; e++) if (sv[e] > sv[i1]) i1 = e;
        int i2 = (i1 == 0) ? 1 : 0;
#pragma unroll
        for (int e = 0; e < 8; e++) if (e != i1 && sv[e] > sv[i2]) i2 = e;
        float wa = sv[i1], wb = sv[i2];
        float wi = 1.0f / (wa + wb + 1e-6f);
        int p1 = atomicAdd(&g_cnt[i1], 1);
        g_etok[i1 * N_TOK + p1] = n;
        g_ew[i1 * N_TOK + p1] = wa * wi;
        g_eslot[i1 * N_TOK + p1] = 2 * n;
        int p2 = atomicAdd(&g_cnt[i2], 1);
        g_etok[i2 * N_TOK + p2] = n;
        g_ew[i2 * N_TOK + p2] = wb * wi;
        g_eslot[i2 * N_TOK + p2] = 2 * n + 1;
        g_sg[n] = 1.0f / (1.0f + expf(-logits[8]));
    }
}

// ---------------- aux loss ----------------
__global__ void k_aux(float* __restrict__ out, int out_size) {
    const int tid = threadIdx.x;
    __shared__ float red[256];
    __shared__ float ssum[8];
    float loc[8] = {0, 0, 0, 0, 0, 0, 0, 0};
    for (int n = tid; n < N_TOK; n += 256) {
#pragma unroll
        for (int e = 0; e < 8; e++) loc[e] += g_scores[n * 8 + e];
    }
#pragma unroll 1
    for (int e = 0; e < 8; e++) {
        red[tid] = loc[e];
        __syncthreads();
        for (int s = 128; s > 0; s >>= 1) {
            if (tid < s) red[tid] += red[tid + s];
            __syncthreads();
        }
        if (tid == 0) ssum[e] = red[0];
        __syncthreads();
    }
    if (tid == 0) {
        float aux = 0.0f;
#pragma unroll
        for (int e = 0; e < 8; e++)
            aux += ((float)g_cnt[e] * 0.5f / N_TOK) * (ssum[e] / N_TOK);
        aux *= (float)E_NUM * 0.01f;
        if (out_size > N_TOK * C_DIM) out[N_TOK * C_DIM] = aux;
    }
}

// ---------------- fp32 -> bf16 hi/lo split conversion ----------------
template <int W>
__global__ void k_conv(const float4* __restrict__ src, int n4) {
    __nv_bfloat162* dh;
    __nv_bfloat162* dl;
    if (W == 0) { dh = (__nv_bfloat162*)g_w1h; dl = (__nv_bfloat162*)g_w1l; }
    else if (W == 1) { dh = (__nv_bfloat162*)g_w2h; dl = (__nv_bfloat162*)g_w2l; }
    else if (W == 2) { dh = (__nv_bfloat162*)g_kwh; dl = (__nv_bfloat162*)g_kwl; }
    else { dh = (__nv_bfloat162*)g_vwh; dl = (__nv_bfloat162*)g_vwl; }
    int stride = gridDim.x * blockDim.x;
    for (int i = blockIdx.x * blockDim.x + threadIdx.x; i < n4; i += stride) {
        float4 v = src[i];
        __nv_bfloat16 h0 = __float2bfloat16(v.x), h1 = __float2bfloat16(v.y);
        __nv_bfloat16 h2 = __float2bfloat16(v.z), h3 = __float2bfloat16(v.w);
        dh[2 * i] = __halves2bfloat162(h0, h1);
        dh[2 * i + 1] = __halves2bfloat162(h2, h3);
        dl[2 * i] = __halves2bfloat162(__float2bfloat16(v.x - __bfloat162float(h0)),
                                       __float2bfloat16(v.y - __bfloat162float(h1)));
        dl[2 * i + 1] = __halves2bfloat162(__float2bfloat16(v.z - __bfloat162float(h2)),
                                           __float2bfloat16(v.w - __bfloat162float(h3)));
    }
}

// ================= HMMA split-bf16 GEMM =================
// CTA tile 128 x TN, BK=32, 256 thr (8 warps, 2x4 -> warp tile 64 x TN/4).
// 3-pass split: Ah*Bh + Ah*Bl + Al*Bh, fp32 accum (mma.sync m16n8k16 bf16).
#define BKC 32
#define ROWB 80                  // smem row stride bytes (16B-mult, conflict-free ldmatrix)

// MODE 0: expert up   A=xt  B=w1[e] K=1024 -> h (relu^2 * w, split bf16)
// MODE 1: expert down A=h   B=w2[e] K=2048 -> contrib (fp32)
// MODE 2: shared up   A=xs  B=kw    K=1024 -> kk ((x+b) relu^2, split bf16)
// MODE 3: shared down A=kk  B=vw    K=2048 -> out = sg*(x+b)
template <int MODE, int TN>
__global__ void __launch_bounds__(256, 1) k_mma(const float* __restrict__ bias,
                                                float* __restrict__ outp) {
    constexpr int NF = TN / 32;               // n-frags per warp (warp N = TN/4)
    constexpr int WN = TN / 4;                // per-warp N extent
    constexpr int A_SZ = 128 * ROWB;
    constexpr int B_SZ = TN * ROWB;
    constexpr int SA_H = 0;
    constexpr int SA_L = A_SZ;
    constexpr int SB_H = 2 * A_SZ;
    constexpr int SB_L = 2 * A_SZ + B_SZ;
    constexpr int BUF_SZ = 2 * A_SZ + 2 * B_SZ;

    extern __shared__ char dsm[];
    __shared__ int s_row[128];
    __shared__ int s_slot[128];
    __shared__ float s_w[128];

    const int e = blockIdx.z;
    const int cnt = (MODE < 2) ? g_cnt[e] : N_TOK;
    const int m0 = blockIdx.y * 128;
    if (m0 >= cnt) return;
    const int n0 = blockIdx.x * TN;
    const int K = (MODE == 0 || MODE == 2) ? C_DIM : H_DIM;

    const __nv_bfloat16 *Ah, *Al, *Bh, *Bl;
    if (MODE == 0) {
        Ah = g_xth; Al = g_xtl;
        Bh = g_w1h + (size_t)e * H_DIM * C_DIM;
        Bl = g_w1l + (size_t)e * H_DIM * C_DIM;
    } else if (MODE == 1) {
        Ah = g_hh; Al = g_hl;
        Bh = g_w2h + (size_t)e * C_DIM * H_DIM;
        Bl = g_w2l + (size_t)e * C_DIM * H_DIM;
    } else if (MODE == 2) {
        Ah = g_xsh; Al = g_xsl; Bh = g_kwh; Bl = g_kwl;
    } else {
        Ah = g_kkh; Al = g_kkl; Bh = g_vwh; Bl = g_vwl;
    }

    const int tid = threadIdx.x, wid = tid >> 5, lid = tid & 31;
    const int wm = wid >> 2, wn = wid & 3;   // warp grid 2(M) x 4(N)

    if (tid < 128) {
        int mi = m0 + tid;
        if (mi >= cnt) mi = cnt - 1;
        if (MODE == 0) {
            s_row[tid] = g_etok[e * N_TOK + mi];
            s_slot[tid] = g_eslot[e * N_TOK + mi];
            s_w[tid] = g_ew[e * N_TOK + mi];
        } else if (MODE == 1) {
            int sl = g_eslot[e * N_TOK + mi];
            s_row[tid] = sl;
            s_slot[tid] = sl;
        } else {
            s_row[tid] = mi;
        }
    }
    __syncthreads();

    const unsigned sbase = smem_u32(dsm);
    const int lr = tid >> 2;          // row group for loads
    const int lcb = (tid & 3) << 4;   // byte col 0/16/32/48
    const int lce = (tid & 3) << 3;   // elem col

    auto load_chunk = [&](int c, int b) {
        const int kc = c * BKC;
        const unsigned bufb = sbase + b * BUF_SZ;
#pragma unroll
        for (int i = 0; i < 2; i++) {           // A: 128 rows
            const int r = lr + i * 64;
            const unsigned so = r * ROWB + lcb;
            const size_t ga = (size_t)s_row[r] * K + kc + lce;
            CP16(bufb + SA_H + so, Ah + ga);
            CP16(bufb + SA_L + so, Al + ga);
        }
#pragma unroll
        for (int i = 0; i < TN / 64; i++) {     // B: TN rows
            const int r = lr + i * 64;
            const unsigned so = r * ROWB + lcb;
            const size_t gb = (size_t)(n0 + r) * K + kc + lce;
            CP16(bufb + SB_H + so, Bh + gb);
            CP16(bufb + SB_L + so, Bl + gb);
        }
        CP_COMMIT();
    };

    float acc[4][NF][4];
#pragma unroll
    for (int i = 0; i < 4; i++)
#pragma unroll
        for (int j = 0; j < NF; j++)
#pragma unroll
            for (int q = 0; q < 4; q++) acc[i][j][q] = 0.0f;

    const unsigned aoff = (unsigned)((wm * 64 + (lid & 7) + ((lid >> 3) & 1) * 8) * ROWB +
                                     ((lid >> 4) & 1) * 16);
    const unsigned boff = (unsigned)((wn * WN + (lid & 7) + ((lid >> 4) & 1) * 8) * ROWB +
                                     ((lid >> 3) & 1) * 16);
    const int NC = K / BKC;
    load_chunk(0, 0);

    for (int c = 0; c < NC; c++) {
        const int b = c & 1;
        if (c + 1 < NC) { load_chunk(c + 1, b ^ 1); CP_WAIT1(); }
        else CP_WAIT0();
        __syncthreads();
        const unsigned bufb = sbase + b * BUF_SZ;
#pragma unroll
        for (int k16 = 0; k16 < 2; k16++) {
            const unsigned kb = k16 * 32;
            unsigned ah[4][4], al[4][4], bh[NF][2], bl[NF][2];
#pragma unroll
            for (int mt = 0; mt < 4; mt++) {
                const unsigned a = bufb + aoff + mt * (16 * ROWB) + kb;
                ldsm4(ah[mt][0], ah[mt][1], ah[mt][2], ah[mt][3], a + SA_H);
                ldsm4(al[mt][0], al[mt][1], al[mt][2], al[mt][3], a + SA_L);
            }
#pragma unroll
            for (int pr = 0; pr < NF / 2; pr++) {
                const unsigned a = bufb + boff + pr * (16 * ROWB) + kb;
                ldsm4(bh[2 * pr][0], bh[2 * pr][1], bh[2 * pr + 1][0], bh[2 * pr + 1][1], a + SB_H);
                ldsm4(bl[2 * pr][0], bl[2 * pr][1], bl[2 * pr + 1][0], bl[2 * pr + 1][1], a + SB_L);
            }
#pragma unroll
            for (int mt = 0; mt < 4; mt++)
#pragma unroll
                for (int nt = 0; nt < NF; nt++) {
                    hmma(acc[mt][nt], ah[mt], bh[nt]);
                    hmma(acc[mt][nt], ah[mt], bl[nt]);
                    hmma(acc[mt][nt], al[mt], bh[nt]);
                }
        }
        __syncthreads();
    }

    // ---------------- epilogue ----------------
    const int rbase = wm * 64 + (lid >> 2);
    const int cbase = n0 + wn * WN + 2 * (lid & 3);
#pragma unroll
    for (int mt = 0; mt < 4; mt++) {
#pragma unroll
        for (int half = 0; half < 2; half++) {
            const int rl = rbase + mt * 16 + half * 8;   // local row 0..127
            if (MODE < 2 && m0 + rl >= cnt) continue;
#pragma unroll
            for (int nt = 0; nt < NF; nt++) {
                const int cg = cbase + nt * 8;
                float v0 = acc[mt][nt][2 * half];
                float v1 = acc[mt][nt][2 * half + 1];
                if (MODE == 0) {
                    const float w = s_w[rl];
                    const int slot = s_slot[rl];
                    v0 = fmaxf(v0, 0.0f); v0 = v0 * v0 * w;
                    v1 = fmaxf(v1, 0.0f); v1 = v1 * v1 * w;
                    __nv_bfloat16 h0 = __float2bfloat16(v0), h1 = __float2bfloat16(v1);
                    *(__nv_bfloat162*)(g_hh + (size_t)slot * H_DIM + cg) = __halves2bfloat162(h0, h1);
                    *(__nv_bfloat162*)(g_hl + (size_t)slot * H_DIM + cg) =
                        __halves2bfloat162(__float2bfloat16(v0 - __bfloat162float(h0)),
                                           __float2bfloat16(v1 - __bfloat162float(h1)));
                } else if (MODE == 1) {
                    const int slot = s_slot[rl];
                    *(float2*)(g_contrib + (size_t)slot * C_DIM + cg) = make_float2(v0, v1);
                } else if (MODE == 2) {
                    const int m = m0 + rl;
                    v0 += bias[cg]; v1 += bias[cg + 1];
                    v0 = fmaxf(v0, 0.0f); v0 = v0 * v0;
                    v1 = fmaxf(v1, 0.0f); v1 = v1 * v1;
                    __nv_bfloat16 h0 = __float2bfloat16(v0), h1 = __float2bfloat16(v1);
                    *(__nv_bfloat162*)(g_kkh + (size_t)m * H_DIM + cg) = __halves2bfloat162(h0, h1);
                    *(__nv_bfloat162*)(g_kkl + (size_t)m * H_DIM + cg) =
                        __halves2bfloat162(__float2bfloat16(v0 - __bfloat162float(h0)),
                                           __float2bfloat16(v1 - __bfloat162float(h1)));
                } else {
                    const int m = m0 + rl;
                    const float sg = g_sg[m];
                    *(float2*)(outp + (size_t)m * C_DIM + cg) =
                        make_float2(sg * (v0 + bias[cg]), sg * (v1 + bias[cg + 1]));
                }
            }
        }
    }
}

// ---- final combine: out += contrib[2n] + contrib[2n+1] ----
__global__ void k_combine(float* __restrict__ out) {
    const int n = blockIdx.x;
    const int tid = threadIdx.x;
    float4* o = reinterpret_cast<float4*>(out + (size_t)n * C_DIM);
    const float4* c0 = reinterpret_cast<const float4*>(g_contrib + (size_t)(2 * n) * C_DIM);
    const float4* c1 = reinterpret_cast<const float4*>(g_contrib + (size_t)(2 * n + 1) * C_DIM);
    float4 a = o[tid], b = c0[tid], c = c1[tid];
    a.x += b.x + c.x;
    a.y += b.y + c.y;
    a.z += b.z + c.z;
    a.w += b.w + c.w;
    o[tid] = a;
}

// ---------------- launch ----------------
#define SMEM_256 (2 * (2 * 128 * ROWB + 2 * 256 * ROWB))   // 122880
#define SMEM_128 (2 * (2 * 128 * ROWB + 2 * 128 * ROWB))   // 81920

extern "C" void kernel_launch(void* const* d_in, const int* in_sizes, int n_in,
                              void* d_out, int out_size) {
    const float* x   = (const float*)d_in[0];
    const float* gw  = (const float*)d_in[1];
    const float* w1  = (const float*)d_in[2];
    const float* w2  = (const float*)d_in[3];
    const float* sgw = (const float*)d_in[4];
    const float* kw  = (const float*)d_in[5];
    const float* kb  = (const float*)d_in[6];
    const float* vw  = (const float*)d_in[7];
    const float* vb  = (const float*)d_in[8];
    float* out = (float*)d_out;

    static int attr_done = 0;
    if (!attr_done) {
        cudaFuncSetAttribute(k_mma<0, 256>, cudaFuncAttributeMaxDynamicSharedMemorySize, SMEM_256);
        cudaFuncSetAttribute(k_mma<1, 256>, cudaFuncAttributeMaxDynamicSharedMemorySize, SMEM_256);
        cudaFuncSetAttribute(k_mma<2, 256>, cudaFuncAttributeMaxDynamicSharedMemorySize, SMEM_256);
        cudaFuncSetAttribute(k_mma<3, 128>, cudaFuncAttributeMaxDynamicSharedMemorySize, SMEM_128);
        attr_done = 1;
    }

    k_zero<<<1, 32>>>();
    k_gate<<<N_TOK, 256>>>(x, gw, sgw);
    k_aux<<<1, 256>>>(out, out_size);

    k_conv<0><<<2048, 256>>>((const float4*)w1, E_NUM * H_DIM * C_DIM / 4);
    k_conv<1><<<2048, 256>>>((const float4*)w2, E_NUM * C_DIM * H_DIM / 4);
    k_conv<2><<<256, 256>>>((const float4*)kw, H_DIM * C_DIM / 4);
    k_conv<3><<<256, 256>>>((const float4*)vw, C_DIM * H_DIM / 4);

    k_mma<0, 256><<<dim3(8, 16, 8), 256, SMEM_256>>>(nullptr, nullptr);  // expert up
    k_mma<2, 256><<<dim3(8, 16, 1), 256, SMEM_256>>>(kb, nullptr);       // shared up
    k_mma<1, 256><<<dim3(4, 16, 8), 256, SMEM_256>>>(nullptr, nullptr);  // expert down
    k_mma<3, 128><<<dim3(8, 16, 1), 256, SMEM_128>>>(vb, out);           // shared down
    k_combine<<<N_TOK, 256>>>(out);
}